// round 5
// baseline (speedup 1.0000x reference)
#include <cuda_runtime.h>
#include <cstdint>

#define BATCH        8192
#define CHAN         4096
#define KWIN         5
#define CH_TILE      1024          // channels per CTA (8 warps * 128)
#define THREADS      256
#define WARPS        8
#define DEPTH        8             // pipeline stages
#define ROWS_PER_CTA 32
#define SLOTS        34            // per-warp strip: [halo_l][32 main][halo_r] float4

__device__ __forceinline__ void cp_async16(void* smem, const void* gmem) {
    unsigned s = (unsigned)__cvta_generic_to_shared(smem);
    asm volatile("cp.async.cg.shared.global [%0], [%1], 16;" :: "r"(s), "l"(gmem));
}
__device__ __forceinline__ void cp_commit() {
    asm volatile("cp.async.commit_group;");
}
template <int N>
__device__ __forceinline__ void cp_wait() {
    asm volatile("cp.async.wait_group %0;" :: "n"(N));
}

// out[b,i] = sum_k W[i,k] * x[b, i+k-2] (zero-padded) + bias[i]
// Warp-private smem strips: each warp owns 128 channels + 4-ch halos per stage,
// so the pipeline needs only __syncwarp (no CTA barriers). 8-deep cp.async
// pipeline keeps ~30KB/CTA of DRAM reads in flight.
__global__ __launch_bounds__(THREADS) void grouped_linear_kernel(
    const float* __restrict__ x,
    const float* __restrict__ W,
    const float* __restrict__ bias,
    float* __restrict__ out)
{
    __shared__ float4 smem[DEPTH * WARPS * SLOTS];   // 34816 B

    const int t    = threadIdx.x;
    const int wid  = t >> 5;
    const int lane = t & 31;
    const int c0   = blockIdx.x * CH_TILE;
    const int cw   = c0 + wid * 128;            // warp's channel base
    const int c    = cw + lane * 4;             // thread's channels
    const int row0 = blockIdx.y * ROWS_PER_CTA;

    const bool has_left  = (cw > 0);
    const bool has_right = (cw + 128 < CHAN);

    // ---- per-thread constants: W[c..c+3][0..4] (20 floats, 16B-aligned) ----
    const float4* wv = reinterpret_cast<const float4*>(W + (size_t)c * KWIN);
    const float4 wa = wv[0];
    const float4 wb = wv[1];
    const float4 wc = wv[2];
    const float4 wd = wv[3];
    const float4 we = wv[4];
    const float4 bb = *reinterpret_cast<const float4*>(bias + c);

    // ---- zero this warp's halo slots in all stages (edge warps keep zeros) ----
    if (lane < DEPTH) {
        float4* sp = smem + (lane * WARPS + wid) * SLOTS;
        sp[0]         = make_float4(0.f, 0.f, 0.f, 0.f);
        sp[SLOTS - 1] = make_float4(0.f, 0.f, 0.f, 0.f);
    }
    __syncwarp();

    // gmem: x[row, cw ..] as float4
    const float4* gbase = reinterpret_cast<const float4*>(x + (size_t)row0 * CHAN + cw);
    const size_t  grow  = CHAN / 4;

    auto load_stage = [&](int stage, int r) {
        float4* sp = smem + (stage * WARPS + wid) * SLOTS;
        const float4* gp = gbase + (size_t)r * grow;
        cp_async16(sp + lane + 1, gp + lane);                      // main
        if (lane == 0 && has_left)  cp_async16(sp, gp - 1);        // left halo
        if (lane == 1 && has_right) cp_async16(sp + 33, gp + 32);  // right halo
    };

    // ---- prologue ----
#pragma unroll
    for (int s = 0; s < DEPTH - 1; s++) {
        load_stage(s, s);
        cp_commit();
    }

    float* op = out + (size_t)row0 * CHAN + c;
    int stage = 0;

    for (int i = 0; i < ROWS_PER_CTA; i++) {
        cp_wait<DEPTH - 2>();
        __syncwarp();

        // refill stage consumed last iteration (same-warp only; no hazard:
        // async write lands >>29cyc after the prior iteration's LDS access)
        const int nr = i + DEPTH - 1;
        if (nr < ROWS_PER_CTA) load_stage(stage == 0 ? DEPTH - 1 : stage - 1, nr);
        cp_commit();

        const float4* sp = smem + (stage * WARPS + wid) * SLOTS;
        const float4 s0 = sp[lane];       // x[c-4..c-1]
        const float4 s1 = sp[lane + 1];   // x[c  ..c+3]
        const float4 s2 = sp[lane + 2];   // x[c+4..c+7]

        const float xm2 = s0.z, xm1 = s0.w;
        const float xp4 = s2.x, xp5 = s2.y;

        float4 o;
        o.x = fmaf(wa.x, xm2,  fmaf(wa.y, xm1,  fmaf(wa.z, s1.x,
              fmaf(wa.w, s1.y, fmaf(wb.x, s1.z, bb.x)))));
        o.y = fmaf(wb.y, xm1,  fmaf(wb.z, s1.x, fmaf(wb.w, s1.y,
              fmaf(wc.x, s1.z, fmaf(wc.y, s1.w, bb.y)))));
        o.z = fmaf(wc.z, s1.x, fmaf(wc.w, s1.y, fmaf(wd.x, s1.z,
              fmaf(wd.y, s1.w, fmaf(wd.z, xp4,  bb.z)))));
        o.w = fmaf(wd.w, s1.y, fmaf(we.x, s1.z, fmaf(we.y, s1.w,
              fmaf(we.z, xp4,  fmaf(we.w, xp5,  bb.w)))));

        __stcs(reinterpret_cast<float4*>(op), o);
        op += CHAN;

        stage = (stage == DEPTH - 1) ? 0 : stage + 1;
    }
}

extern "C" void kernel_launch(void* const* d_in, const int* in_sizes, int n_in,
                              void* d_out, int out_size)
{
    const float* x    = (const float*)d_in[0];
    const float* W    = (const float*)d_in[1];
    const float* bias = (const float*)d_in[2];
    float* out        = (float*)d_out;

    dim3 block(THREADS);
    dim3 grid(CHAN / CH_TILE, BATCH / ROWS_PER_CTA);  // (4, 256)
    grouped_linear_kernel<<<grid, block>>>(x, W, bias, out);
}

// round 6
// speedup vs baseline: 1.0548x; 1.0548x over previous
#include <cuda_runtime.h>
#include <cstdint>

#define BATCH        8192
#define CHAN         4096
#define KWIN         5
#define CH_TILE      1024          // channels per CTA (256 threads * 4)
#define THREADS      256
#define DEPTH        8             // stage slots (ring)
#define AHEAD        6             // rows in flight
#define ROWS_PER_CTA 32
#define STAGE_F4     258           // float4 per stage: [halo_l][256 main][halo_r]
#define STAGE_STRIDE 264           // padded stage stride in float4

__device__ __forceinline__ void cp_async16(void* smem, const void* gmem) {
    unsigned s = (unsigned)__cvta_generic_to_shared(smem);
    asm volatile("cp.async.cg.shared.global [%0], [%1], 16;" :: "r"(s), "l"(gmem));
}
__device__ __forceinline__ void cp_commit() {
    asm volatile("cp.async.commit_group;");
}
template <int N>
__device__ __forceinline__ void cp_wait() {
    asm volatile("cp.async.wait_group %0;" :: "n"(N));
}

// out[b,i] = sum_k W[i,k] * x[b, i+k-2] (zero-padded) + bias[i]
// CTA-wide cp.async pipeline, 2 rows per step -> half the barriers of R4.
// Refill targets stages consumed in the PREVIOUS step (reads ordered before
// this step's __syncthreads), 6 rows (~25KB/CTA) outstanding.
__global__ __launch_bounds__(THREADS) void grouped_linear_kernel(
    const float* __restrict__ x,
    const float* __restrict__ W,
    const float* __restrict__ bias,
    float* __restrict__ out)
{
    __shared__ float4 smem[DEPTH * STAGE_STRIDE];   // 33792 B

    const int t    = threadIdx.x;
    const int c0   = blockIdx.x * CH_TILE;
    const int c    = c0 + t * 4;
    const int row0 = blockIdx.y * ROWS_PER_CTA;

    const bool not_first_tile = (blockIdx.x > 0);
    const bool not_last_tile  = (c0 + CH_TILE < CHAN);

    // ---- per-thread constants ----
    const float4* wv = reinterpret_cast<const float4*>(W + (size_t)c * KWIN);
    const float4 wa = wv[0];
    const float4 wb = wv[1];
    const float4 wc = wv[2];
    const float4 wd = wv[3];
    const float4 we = wv[4];
    const float4 bb = *reinterpret_cast<const float4*>(bias + c);

    // zero halo slots once (edge tiles never overwrite them)
    if (t < DEPTH) {
        smem[t * STAGE_STRIDE + 0]            = make_float4(0.f, 0.f, 0.f, 0.f);
        smem[t * STAGE_STRIDE + STAGE_F4 - 1] = make_float4(0.f, 0.f, 0.f, 0.f);
    }
    __syncthreads();

    const float4* gbase = reinterpret_cast<const float4*>(x + (size_t)row0 * CHAN + c0 - 4);
    const size_t  grow  = CHAN / 4;

    auto load_stage = [&](int r) {                      // stage = r % DEPTH
        float4* sp = smem + (r & (DEPTH - 1)) * STAGE_STRIDE;
        const float4* gp = gbase + (size_t)r * grow;
        cp_async16(sp + t + 1, gp + t + 1);
        if (t == 0 && not_first_tile) cp_async16(sp, gp);
        if (t == 1 && not_last_tile)  cp_async16(sp + 257, gp + 257);
    };

    // compute one row from its stage, store
    auto do_row = [&](int r, float* op) {
        const float4* sp = smem + (r & (DEPTH - 1)) * STAGE_STRIDE;
        const float4 s0 = sp[t];
        const float4 s1 = sp[t + 1];
        const float4 s2 = sp[t + 2];
        const float xm2 = s0.z, xm1 = s0.w;
        const float xp4 = s2.x, xp5 = s2.y;

        float4 o;
        o.x = fmaf(wa.x, xm2,  fmaf(wa.y, xm1,  fmaf(wa.z, s1.x,
              fmaf(wa.w, s1.y, fmaf(wb.x, s1.z, bb.x)))));
        o.y = fmaf(wb.y, xm1,  fmaf(wb.z, s1.x, fmaf(wb.w, s1.y,
              fmaf(wc.x, s1.z, fmaf(wc.y, s1.w, bb.y)))));
        o.z = fmaf(wc.z, s1.x, fmaf(wc.w, s1.y, fmaf(wd.x, s1.z,
              fmaf(wd.y, s1.w, fmaf(wd.z, xp4,  bb.z)))));
        o.w = fmaf(wd.w, s1.y, fmaf(we.x, s1.z, fmaf(we.y, s1.w,
              fmaf(we.z, xp4,  fmaf(we.w, xp5,  bb.w)))));
        __stcs(reinterpret_cast<float4*>(op), o);
    };

    // ---- prologue: rows 0..AHEAD-1 (one commit each) ----
#pragma unroll
    for (int r = 0; r < AHEAD; r++) {
        load_stage(r);
        cp_commit();
    }

    float* op = out + (size_t)row0 * CHAN + c;

#pragma unroll 4
    for (int i = 0; i < ROWS_PER_CTA; i += 2) {
        cp_wait<AHEAD - 2>();          // rows i, i+1 complete (this thread)
        __syncthreads();               // ... all threads; also fences prior reads

        // refill stages consumed last step (rows i-2, i-1 slots)
        if (i + AHEAD     < ROWS_PER_CTA) load_stage(i + AHEAD);
        cp_commit();
        if (i + AHEAD + 1 < ROWS_PER_CTA) load_stage(i + AHEAD + 1);
        cp_commit();

        do_row(i,     op);
        do_row(i + 1, op + CHAN);
        op += 2 * CHAN;
    }
}

extern "C" void kernel_launch(void* const* d_in, const int* in_sizes, int n_in,
                              void* d_out, int out_size)
{
    const float* x    = (const float*)d_in[0];
    const float* W    = (const float*)d_in[1];
    const float* bias = (const float*)d_in[2];
    float* out        = (float*)d_out;

    dim3 block(THREADS);
    dim3 grid(CHAN / CH_TILE, BATCH / ROWS_PER_CTA);  // (4, 256)
    grouped_linear_kernel<<<grid, block>>>(x, W, bias, out);
}